// round 4
// baseline (speedup 1.0000x reference)
#include <cuda_runtime.h>
#include <cuda_bf16.h>

// SmoothnessLoss: loss = mean_i( (sHat_i - sY_i)^2 ), i in [0, W), W = N-k-1
// s_i = sum_{j<k} | x[i+j] - mean_j |, k = 64.
// Persistent kernel, fused deterministic reduction, 4-way split accumulators for ILP.

#define K_WIN 64
#define BLOCK 256
#define WPT 4
#define SUBTILE (BLOCK * WPT)                // 1024 windows per subtile
#define TILE_ELEMS (SUBTILE + K_WIN)         // 1088 floats
#define TILE_F4 (TILE_ELEMS / 4)             // 272
#define CHUNKS 17                            // float4 per thread segment (68 floats)
#define GRID 296                             // 2 blocks/SM x 148 SMs

typedef unsigned long long u64;

__device__ float g_partials[GRID];
__device__ unsigned int g_count = 0;

__device__ __forceinline__ u64 addx2(u64 a, u64 b) {
    u64 r; asm("add.rn.f32x2 %0, %1, %2;" : "=l"(r) : "l"(a), "l"(b)); return r;
}
__device__ __forceinline__ u64 pk(float lo, float hi) {
    u64 r; asm("mov.b64 %0, {%1, %2};" : "=l"(r) : "f"(lo), "f"(hi)); return r;
}
__device__ __forceinline__ void upk(u64 p, float& lo, float& hi) {
    asm("mov.b64 {%0, %1}, %2;" : "=f"(lo), "=f"(hi) : "l"(p));
}
__device__ __forceinline__ u64 absx2(u64 a) { return a & 0x7FFFFFFF7FFFFFFFULL; }

// One array's 68-float segment: 4 window sums -> 4 abs-deviation sums.
// All reduction loops use 4 independent accumulators (chain depth 32 -> 8).
__device__ __forceinline__ void process_seg(const ulonglong2* __restrict__ t2, int tid,
                                            float a[WPT])
{
    u64 v[2 * CHUNKS];                 // 34 packed pairs = 68 floats
    #pragma unroll
    for (int q = 0; q < CHUNKS; q++) {
        ulonglong2 c = t2[tid + q];
        v[2 * q]     = c.x;
        v[2 * q + 1] = c.y;
    }

    // Pass 1: sum of elements [0,64) -- 4 parallel chains of 8.
    u64 t0 = v[0], t1 = v[1], t2a = v[2], t3 = v[3];
    #pragma unroll
    for (int p = 1; p < 8; p++) {
        t0  = addx2(t0,  v[4 * p]);
        t1  = addx2(t1,  v[4 * p + 1]);
        t2a = addx2(t2a, v[4 * p + 2]);
        t3  = addx2(t3,  v[4 * p + 3]);
    }
    u64 acc = addx2(addx2(t0, t1), addx2(t2a, t3));
    float lo, hi; upk(acc, lo, hi);

    float s[WPT];
    s[0] = lo + hi;
    // Sliding updates with shallow dependence on s[0].
    float e0, e1, e2, e3, f0, f1, f2, f3;
    upk(v[0],  e0, e1); upk(v[1],  e2, e3);   // elements 0..3
    upk(v[32], f0, f1); upk(v[33], f2, f3);   // elements 64..67
    const float d0 = f0 - e0;
    const float d1 = f1 - e1;
    const float d2s = f2 - e2;
    s[1] = s[0] + d0;
    s[2] = s[0] + (d0 + d1);
    s[3] = s[0] + ((d0 + d1) + d2s);
    (void)e3; (void)f3;

    const float invk = 1.0f / (float)K_WIN;

    // Pass 2: per window w, sum |x - m| -- 4 parallel chains per window.
    #pragma unroll
    for (int w = 0; w < WPT; w++) {
        const float m = s[w] * invk;
        const u64 nm2 = pk(-m, -m);
        u64 a0 = 0ULL, a1p = 0ULL, a2p = 0ULL, a3p = 0ULL;
        float extra = 0.0f;
        if ((w & 1) == 0) {
            const int p0 = w >> 1;             // 32 aligned pairs
            #pragma unroll
            for (int p = 0; p < 8; p++) {
                a0  = addx2(a0,  absx2(addx2(v[p0 + 4 * p],     nm2)));
                a1p = addx2(a1p, absx2(addx2(v[p0 + 4 * p + 1], nm2)));
                a2p = addx2(a2p, absx2(addx2(v[p0 + 4 * p + 2], nm2)));
                a3p = addx2(a3p, absx2(addx2(v[p0 + 4 * p + 3], nm2)));
            }
        } else {
            const int p0 = (w + 1) >> 1;       // 31 aligned interior pairs
            #pragma unroll
            for (int p = 0; p < 7; p++) {
                a0  = addx2(a0,  absx2(addx2(v[p0 + 4 * p],     nm2)));
                a1p = addx2(a1p, absx2(addx2(v[p0 + 4 * p + 1], nm2)));
                a2p = addx2(a2p, absx2(addx2(v[p0 + 4 * p + 2], nm2)));
                a3p = addx2(a3p, absx2(addx2(v[p0 + 4 * p + 3], nm2)));
            }
            a0  = addx2(a0,  absx2(addx2(v[p0 + 28], nm2)));
            a1p = addx2(a1p, absx2(addx2(v[p0 + 29], nm2)));
            a2p = addx2(a2p, absx2(addx2(v[p0 + 30], nm2)));
            float q0, q1, x0, x1;
            upk(v[w >> 1], q0, q1);        x0 = q1;   // element w (odd -> hi half)
            upk(v[(w + 63) >> 1], q0, q1); x1 = q0;   // element w+63 (even -> lo half)
            extra = fabsf(x0 - m) + fabsf(x1 - m);
        }
        u64 aa = addx2(addx2(a0, a1p), addx2(a2p, a3p));
        float al, ah; upk(aa, al, ah);
        a[w] = (al + ah) + extra;
    }
}

__global__ void __launch_bounds__(BLOCK, 2)
smoothness_persist_kernel(const float* __restrict__ yh,
                          const float* __restrict__ yy,
                          int W, int N, int WB,
                          float* __restrict__ out, double invW)
{
    __shared__ float4 sh4[TILE_F4];
    __shared__ float4 sy4[TILE_F4];
    __shared__ float  redf[BLOCK / 32];
    __shared__ double redd[BLOCK / 32];
    __shared__ int    amLast;

    const int tid    = threadIdx.x;
    const int wstart = blockIdx.x * WB;            // multiple of 4
    const int wend   = min(wstart + WB, W);

    float d2 = 0.0f;

    for (int base = wstart; base < wend; base += SUBTILE) {
        const int b4 = base >> 2;
        #pragma unroll
        for (int q = tid; q < TILE_F4; q += BLOCK) {
            const int g = base + 4 * q;
            float4 vh, vy;
            if (g + 3 < N) {
                vh = reinterpret_cast<const float4*>(yh)[b4 + q];
                vy = reinterpret_cast<const float4*>(yy)[b4 + q];
            } else {
                float h[4], y[4];
                #pragma unroll
                for (int j = 0; j < 4; j++) {
                    const bool ok = (g + j) < N;
                    h[j] = ok ? yh[g + j] : 0.0f;
                    y[j] = ok ? yy[g + j] : 0.0f;
                }
                vh = make_float4(h[0], h[1], h[2], h[3]);
                vy = make_float4(y[0], y[1], y[2], y[3]);
            }
            sh4[q] = vh;
            sy4[q] = vy;
        }
        __syncthreads();

        const int i0 = base + WPT * tid;
        if (i0 < wend) {
            float a1[WPT], a2[WPT];
            process_seg(reinterpret_cast<const ulonglong2*>(sh4), tid, a1);
            process_seg(reinterpret_cast<const ulonglong2*>(sy4), tid, a2);
            #pragma unroll
            for (int w = 0; w < WPT; w++) {
                if (i0 + w < wend) {
                    const float d = a1[w] - a2[w];
                    d2 += d * d;
                }
            }
        }
        __syncthreads();
    }

    // Block reduction of d2.
    #pragma unroll
    for (int off = 16; off > 0; off >>= 1)
        d2 += __shfl_down_sync(0xffffffffu, d2, off);

    const int lane = tid & 31, wid = tid >> 5;
    if (lane == 0) redf[wid] = d2;
    __syncthreads();
    if (wid == 0) {
        float v = (lane < BLOCK / 32) ? redf[lane] : 0.0f;
        #pragma unroll
        for (int off = 4; off > 0; off >>= 1)
            v += __shfl_down_sync(0xffffffffu, v, off);
        if (lane == 0) {
            g_partials[blockIdx.x] = v;
            __threadfence();
            unsigned int c = atomicAdd(&g_count, 1u);
            amLast = (c == (unsigned int)(gridDim.x - 1));
        }
    }
    __syncthreads();

    if (amLast) {
        double s = 0.0;
        for (int i = tid; i < GRID; i += BLOCK)
            s += (double)g_partials[i];
        #pragma unroll
        for (int off = 16; off > 0; off >>= 1)
            s += __shfl_down_sync(0xffffffffu, s, off);
        if (lane == 0) redd[wid] = s;
        __syncthreads();
        if (wid == 0) {
            double v = (lane < BLOCK / 32) ? redd[lane] : 0.0;
            #pragma unroll
            for (int off = 4; off > 0; off >>= 1)
                v += __shfl_down_sync(0xffffffffu, v, off);
            if (lane == 0) {
                out[0] = (float)(v * invW);
                g_count = 0;                 // reset for next graph replay
            }
        }
    }
}

extern "C" void kernel_launch(void* const* d_in, const int* in_sizes, int n_in,
                              void* d_out, int out_size)
{
    const float* yh = (const float*)d_in[0];
    const float* yy = (const float*)d_in[1];
    const int N = in_sizes[0];
    const int W = N - K_WIN - 1;
    int WB = (W + GRID - 1) / GRID;
    WB = (WB + 3) & ~3;

    smoothness_persist_kernel<<<GRID, BLOCK>>>(yh, yy, W, N, WB,
                                               (float*)d_out, 1.0 / (double)W);
}